// round 2
// baseline (speedup 1.0000x reference)
#include <cuda_runtime.h>
#include <math.h>

#define DD 64
#define KK 512
#define NV 65536
#define DECAYF 0.99f
#define EPSF 1e-5f

// Output layout (concatenated, float32, reference tuple order):
// quantized_st [64,32,32,64], loss [1], perplexity [1], encoding_indices [64,32,32],
// new_embeddings [64,512], hid_cs [512], hid_dw [64,512]
#define OFF_Q      0
#define OFF_LOSS   (NV * DD)            // 4194304
#define OFF_PERP   (OFF_LOSS + 1)       // 4194305
#define OFF_IDX    (OFF_PERP + 1)       // 4194306
#define OFF_NEWEMB (OFF_IDX + NV)       // 4259842
#define OFF_HIDCS  (OFF_NEWEMB + DD*KK) // 4292610
#define OFF_HIDDW  (OFF_HIDCS + KK)     // 4293122

// Scratch (no allocations allowed -> device globals)
__device__ float g_dw[DD * KK];
__device__ float g_cs[KK];
__device__ float g_esq[KK];
__device__ float g_loss;

__global__ void k_init(const float* __restrict__ emb) {
    int i = blockIdx.x * blockDim.x + threadIdx.x;
    if (i < DD * KK) g_dw[i] = 0.0f;
    if (i < KK) {
        float s = 0.0f;
        #pragma unroll 8
        for (int d = 0; d < DD; d++) {
            float v = emb[d * KK + i];
            s = fmaf(v, v, s);
        }
        g_esq[i] = s;
        g_cs[i] = 0.0f;
    }
    if (i == 0) g_loss = 0.0f;
}

__global__ void __launch_bounds__(512, 1) k_main(
    const float* __restrict__ x, const float* __restrict__ emb,
    float* __restrict__ out)
{
    extern __shared__ float sm[];
    float* e_s   = sm;            // [DD][KK], natural layout: e_s[d*KK + k]
    float* esq_s = sm + DD * KK;  // [KK]

    {
        const float4* src = (const float4*)emb;
        float4* dst = (float4*)e_s;
        for (int i = threadIdx.x; i < DD * KK / 4; i += blockDim.x) dst[i] = src[i];
        for (int i = threadIdx.x; i < KK; i += blockDim.x) esq_s[i] = g_esq[i];
    }
    __syncthreads();

    int chunk = (NV + gridDim.x - 1) / gridDim.x;         // 432 @ grid=152
    int n = blockIdx.x * chunk + threadIdx.x;
    bool active = (threadIdx.x < chunk) && (n < NV);

    float lsum = 0.0f;
    if (active) {
        float xr[DD];
        const float4* xv = (const float4*)(x + (size_t)n * DD);
        #pragma unroll
        for (int i = 0; i < DD / 4; i++) {
            float4 v = xv[i];
            xr[4*i+0] = v.x; xr[4*i+1] = v.y; xr[4*i+2] = v.z; xr[4*i+3] = v.w;
        }

        float best = 3.4e38f;
        int bidx = 0;
        #pragma unroll 1
        for (int k0 = 0; k0 < KK; k0 += 4) {
            float a0 = 0.f, a1 = 0.f, a2 = 0.f, a3 = 0.f;
            #pragma unroll
            for (int d = 0; d < DD; d++) {
                float4 e4 = *(const float4*)(e_s + d * KK + k0);   // broadcast LDS.128
                a0 = fmaf(xr[d], e4.x, a0);
                a1 = fmaf(xr[d], e4.y, a1);
                a2 = fmaf(xr[d], e4.z, a2);
                a3 = fmaf(xr[d], e4.w, a3);
            }
            // score_k = ||e_k||^2 - 2 x.e_k   (||x||^2 is constant per row; argmin-safe)
            float s0 = fmaf(-2.0f, a0, esq_s[k0 + 0]);
            float s1 = fmaf(-2.0f, a1, esq_s[k0 + 1]);
            float s2 = fmaf(-2.0f, a2, esq_s[k0 + 2]);
            float s3 = fmaf(-2.0f, a3, esq_s[k0 + 3]);
            // ascending + strict < == argmax(-d) first-occurrence tie-break
            if (s0 < best) { best = s0; bidx = k0 + 0; }
            if (s1 < best) { best = s1; bidx = k0 + 1; }
            if (s2 < best) { best = s2; bidx = k0 + 2; }
            if (s3 < best) { best = s3; bidx = k0 + 3; }
        }

        out[OFF_IDX + n] = (float)bidx;
        atomicAdd(&g_cs[bidx], 1.0f);

        float4* qv = (float4*)(out + OFF_Q + (size_t)n * DD);
        #pragma unroll
        for (int d4 = 0; d4 < DD; d4 += 4) {
            float q0 = e_s[(d4 + 0) * KK + bidx];
            float q1 = e_s[(d4 + 1) * KK + bidx];
            float q2 = e_s[(d4 + 2) * KK + bidx];
            float q3 = e_s[(d4 + 3) * KK + bidx];
            float e0 = q0 - xr[d4 + 0], e1 = q1 - xr[d4 + 1];
            float e2 = q2 - xr[d4 + 2], e3 = q3 - xr[d4 + 3];
            lsum = fmaf(e0, e0, lsum); lsum = fmaf(e1, e1, lsum);
            lsum = fmaf(e2, e2, lsum); lsum = fmaf(e3, e3, lsum);
            qv[d4 / 4] = make_float4(q0, q1, q2, q3);
            atomicAdd(&g_dw[(d4 + 0) * KK + bidx], xr[d4 + 0]);
            atomicAdd(&g_dw[(d4 + 1) * KK + bidx], xr[d4 + 1]);
            atomicAdd(&g_dw[(d4 + 2) * KK + bidx], xr[d4 + 2]);
            atomicAdd(&g_dw[(d4 + 3) * KK + bidx], xr[d4 + 3]);
        }
    }

    // full-warp reduction of loss partials (inactive lanes contribute 0)
    #pragma unroll
    for (int o = 16; o > 0; o >>= 1)
        lsum += __shfl_down_sync(0xffffffffu, lsum, o);
    if ((threadIdx.x & 31) == 0 && lsum != 0.0f)
        atomicAdd(&g_loss, lsum);
}

__global__ void k_fin(const float* __restrict__ ema_cs,
                      const float* __restrict__ ema_dw,
                      const int* __restrict__ counter,
                      float* __restrict__ out)
{
    __shared__ float  s_stable[KK];
    __shared__ double s_red[512];
    int t = threadIdx.x;  // exactly KK threads

    double debias = 1.0 - pow(0.99, (double)(counter[0] + 1));

    float cs  = g_cs[t];
    float hid = ema_cs[t] * DECAYF + cs * (1.0f - DECAYF);
    out[OFF_HIDCS + t] = hid;
    float upd = (float)((double)hid / debias);

    // n = sum(updated_ema_cluster_size)
    s_red[t] = (double)upd;
    __syncthreads();
    for (int s = 256; s > 0; s >>= 1) {
        if (t < s) s_red[t] += s_red[t + s];
        __syncthreads();
    }
    double nsum = s_red[0];
    __syncthreads();

    float stable = (float)(((double)upd + (double)EPSF)
                           / (nsum + (double)KK * (double)EPSF) * nsum);
    s_stable[t] = stable;

    // perplexity
    double p = (double)cs / (double)NV;
    s_red[t] = -p * log(p + 1e-10);
    __syncthreads();
    for (int s = 256; s > 0; s >>= 1) {
        if (t < s) s_red[t] += s_red[t + s];
        __syncthreads();
    }
    double ent = s_red[0];

    if (t == 0) {
        out[OFF_PERP] = (float)exp(ent);
        out[OFF_LOSS] = 0.25f * (g_loss / (float)(NV * DD));
    }
    __syncthreads();

    for (int i = t; i < DD * KK; i += blockDim.x) {
        float hdw = ema_dw[i] * DECAYF + g_dw[i] * (1.0f - DECAYF);
        out[OFF_HIDDW + i] = hdw;
        out[OFF_NEWEMB + i] = (float)((double)hdw / debias) / s_stable[i & (KK - 1)];
    }
}

extern "C" void kernel_launch(void* const* d_in, const int* in_sizes, int n_in,
                              void* d_out, int out_size)
{
    const float* x      = (const float*)d_in[0];
    const float* emb    = (const float*)d_in[1];
    const float* ema_cs = (const float*)d_in[2];
    const float* ema_dw = (const float*)d_in[3];
    const int*   counter = (const int*)d_in[4];
    float* out = (float*)d_out;

    const int smem = (DD * KK + KK) * (int)sizeof(float);  // 133,120 B
    cudaFuncSetAttribute(k_main, cudaFuncAttributeMaxDynamicSharedMemorySize, smem);

    k_init<<<(DD * KK + 255) / 256, 256>>>(emb);
    k_main<<<152, 512, smem>>>(x, emb, out);
    k_fin<<<1, KK>>>(ema_cs, ema_dw, counter, out);
}

// round 3
// speedup vs baseline: 1.0551x; 1.0551x over previous
#include <cuda_runtime.h>
#include <math.h>

#define DD 64
#define KK 512
#define NV 65536
#define DECAYF 0.99f
#define EPSF 1e-5f

// Output layout (concatenated, float32, reference tuple order):
// quantized_st [64,32,32,64], loss [1], perplexity [1], encoding_indices [64,32,32],
// new_embeddings [64,512], hid_cs [512], hid_dw [64,512]
#define OFF_Q      0
#define OFF_LOSS   (NV * DD)            // 4194304
#define OFF_PERP   (OFF_LOSS + 1)       // 4194305
#define OFF_IDX    (OFF_PERP + 1)       // 4194306
#define OFF_NEWEMB (OFF_IDX + NV)       // 4259842
#define OFF_HIDCS  (OFF_NEWEMB + DD*KK) // 4292610
#define OFF_HIDDW  (OFF_HIDCS + KK)     // 4293122

typedef unsigned long long ull;

// Packed fp32x2 FMA (Blackwell): 2 IEEE fp32 FMAs per instruction, bit-exact
// vs two scalar fmaf -> argmin identical to scalar reference.
__device__ __forceinline__ ull ffma2(ull a, ull b, ull c) {
    ull d;
    asm("fma.rn.f32x2 %0, %1, %2, %3;" : "=l"(d) : "l"(a), "l"(b), "l"(c));
    return d;
}
__device__ __forceinline__ ull pack2(float lo, float hi) {
    ull r;
    asm("mov.b64 %0, {%1, %2};" : "=l"(r) : "f"(lo), "f"(hi));
    return r;
}
__device__ __forceinline__ float2 unpack2(ull v) {
    float2 f;
    asm("mov.b64 {%0, %1}, %2;" : "=f"(f.x), "=f"(f.y) : "l"(v));
    return f;
}

// Scratch (no allocations allowed -> device globals)
__device__ float g_dw[DD * KK];
__device__ float g_cs[KK];
__device__ float g_loss;

__global__ void k_init() {
    int i = blockIdx.x * blockDim.x + threadIdx.x;   // 8192 threads
    if (i < DD * KK / 4) ((float4*)g_dw)[i] = make_float4(0.f, 0.f, 0.f, 0.f);
    if (i < KK / 4)      ((float4*)g_cs)[i] = make_float4(0.f, 0.f, 0.f, 0.f);
    if (i == 0) g_loss = 0.0f;
}

__global__ void __launch_bounds__(512, 1) k_main(
    const float* __restrict__ x, const float* __restrict__ emb,
    float* __restrict__ out)
{
    extern __shared__ float sm[];
    float* e_s   = sm;            // [DD][KK], natural layout: e_s[d*KK + k]
    float* esq_s = sm + DD * KK;  // [KK]

    {
        const float4* src = (const float4*)emb;
        float4* dst = (float4*)e_s;
        for (int i = threadIdx.x; i < DD * KK / 4; i += blockDim.x) dst[i] = src[i];
    }
    __syncthreads();

    // ||e_k||^2 from smem: lane t handles code t; (d*512+t)%32 distinct per lane
    {
        int k = threadIdx.x;  // 512 threads == KK
        float s = 0.0f;
        #pragma unroll
        for (int d = 0; d < DD; d++) {
            float v = e_s[d * KK + k];
            s = fmaf(v, v, s);
        }
        esq_s[k] = s;
    }
    __syncthreads();

    int chunk = (NV + gridDim.x - 1) / gridDim.x;    // 432 @ grid=152
    int n = blockIdx.x * chunk + threadIdx.x;
    bool active = (threadIdx.x < chunk) && (n < NV);

    float lsum = 0.0f;
    if (active) {
        float xr[DD];
        const float4* xv = (const float4*)(x + (size_t)n * DD);
        #pragma unroll
        for (int i = 0; i < DD / 4; i++) {
            float4 v = xv[i];
            xr[4*i+0] = v.x; xr[4*i+1] = v.y; xr[4*i+2] = v.z; xr[4*i+3] = v.w;
        }

        const ull M2 = pack2(-2.0f, -2.0f);
        float best = 3.4e38f;
        int bidx = 0;

        #pragma unroll 1
        for (int k0 = 0; k0 < KK; k0 += 8) {
            ull a0 = 0ull, a1 = 0ull, a2 = 0ull, a3 = 0ull;  // (0.f,0.f)
            #pragma unroll
            for (int d = 0; d < DD; d++) {
                // broadcast LDS.128 x2: codes k0..k0+7 at row d
                ulonglong2 ea = *(const ulonglong2*)(e_s + d * KK + k0);
                ulonglong2 eb = *(const ulonglong2*)(e_s + d * KK + k0 + 4);
                ull xd = pack2(xr[d], xr[d]);
                a0 = ffma2(xd, ea.x, a0);
                a1 = ffma2(xd, ea.y, a1);
                a2 = ffma2(xd, eb.x, a2);
                a3 = ffma2(xd, eb.y, a3);
            }
            // score_k = ||e_k||^2 - 2 x.e_k   (||x||^2 const per row; argmin-safe)
            const ull* eq = (const ull*)(esq_s + k0);
            float2 s0 = unpack2(ffma2(M2, a0, eq[0]));
            float2 s1 = unpack2(ffma2(M2, a1, eq[1]));
            float2 s2 = unpack2(ffma2(M2, a2, eq[2]));
            float2 s3 = unpack2(ffma2(M2, a3, eq[3]));
            // ascending k + strict < == argmax(-d) first-occurrence tie-break
            if (s0.x < best) { best = s0.x; bidx = k0 + 0; }
            if (s0.y < best) { best = s0.y; bidx = k0 + 1; }
            if (s1.x < best) { best = s1.x; bidx = k0 + 2; }
            if (s1.y < best) { best = s1.y; bidx = k0 + 3; }
            if (s2.x < best) { best = s2.x; bidx = k0 + 4; }
            if (s2.y < best) { best = s2.y; bidx = k0 + 5; }
            if (s3.x < best) { best = s3.x; bidx = k0 + 6; }
            if (s3.y < best) { best = s3.y; bidx = k0 + 7; }
        }

        out[OFF_IDX + n] = (float)bidx;
        atomicAdd(&g_cs[bidx], 1.0f);

        float4* qv = (float4*)(out + OFF_Q + (size_t)n * DD);
        #pragma unroll
        for (int d4 = 0; d4 < DD; d4 += 4) {
            float q0 = e_s[(d4 + 0) * KK + bidx];
            float q1 = e_s[(d4 + 1) * KK + bidx];
            float q2 = e_s[(d4 + 2) * KK + bidx];
            float q3 = e_s[(d4 + 3) * KK + bidx];
            float e0 = q0 - xr[d4 + 0], e1 = q1 - xr[d4 + 1];
            float e2 = q2 - xr[d4 + 2], e3 = q3 - xr[d4 + 3];
            lsum = fmaf(e0, e0, lsum); lsum = fmaf(e1, e1, lsum);
            lsum = fmaf(e2, e2, lsum); lsum = fmaf(e3, e3, lsum);
            qv[d4 / 4] = make_float4(q0, q1, q2, q3);
            atomicAdd(&g_dw[(d4 + 0) * KK + bidx], xr[d4 + 0]);
            atomicAdd(&g_dw[(d4 + 1) * KK + bidx], xr[d4 + 1]);
            atomicAdd(&g_dw[(d4 + 2) * KK + bidx], xr[d4 + 2]);
            atomicAdd(&g_dw[(d4 + 3) * KK + bidx], xr[d4 + 3]);
        }
    }

    // full-warp reduction of loss partials (inactive lanes contribute 0)
    #pragma unroll
    for (int o = 16; o > 0; o >>= 1)
        lsum += __shfl_down_sync(0xffffffffu, lsum, o);
    if ((threadIdx.x & 31) == 0 && lsum != 0.0f)
        atomicAdd(&g_loss, lsum);
}

__global__ void k_fin(const float* __restrict__ ema_cs,
                      const float* __restrict__ ema_dw,
                      const int* __restrict__ counter,
                      float* __restrict__ out)
{
    __shared__ float  s_stable[KK];
    __shared__ double s_red[512];
    int t = threadIdx.x;  // exactly KK threads

    double debias = 1.0 - pow(0.99, (double)(counter[0] + 1));

    float cs  = g_cs[t];
    float hid = ema_cs[t] * DECAYF + cs * (1.0f - DECAYF);
    out[OFF_HIDCS + t] = hid;
    float upd = (float)((double)hid / debias);

    // n = sum(updated_ema_cluster_size)
    s_red[t] = (double)upd;
    __syncthreads();
    for (int s = 256; s > 0; s >>= 1) {
        if (t < s) s_red[t] += s_red[t + s];
        __syncthreads();
    }
    double nsum = s_red[0];
    __syncthreads();

    float stable = (float)(((double)upd + (double)EPSF)
                           / (nsum + (double)KK * (double)EPSF) * nsum);
    s_stable[t] = stable;

    // perplexity
    double p = (double)cs / (double)NV;
    s_red[t] = -p * log(p + 1e-10);
    __syncthreads();
    for (int s = 256; s > 0; s >>= 1) {
        if (t < s) s_red[t] += s_red[t + s];
        __syncthreads();
    }
    double ent = s_red[0];

    if (t == 0) {
        out[OFF_PERP] = (float)exp(ent);
        out[OFF_LOSS] = 0.25f * (g_loss / (float)(NV * DD));
    }
    __syncthreads();

    for (int i = t; i < DD * KK; i += blockDim.x) {
        float hdw = ema_dw[i] * DECAYF + g_dw[i] * (1.0f - DECAYF);
        out[OFF_HIDDW + i] = hdw;
        out[OFF_NEWEMB + i] = (float)((double)hdw / debias) / s_stable[i & (KK - 1)];
    }
}

extern "C" void kernel_launch(void* const* d_in, const int* in_sizes, int n_in,
                              void* d_out, int out_size)
{
    const float* x       = (const float*)d_in[0];
    const float* emb     = (const float*)d_in[1];
    const float* ema_cs  = (const float*)d_in[2];
    const float* ema_dw  = (const float*)d_in[3];
    const int*   counter = (const int*)d_in[4];
    float* out = (float*)d_out;

    const int smem = (DD * KK + KK) * (int)sizeof(float);  // 133,120 B
    cudaFuncSetAttribute(k_main, cudaFuncAttributeMaxDynamicSharedMemorySize, smem);

    k_init<<<16, 512>>>();
    k_main<<<152, 512, smem>>>(x, emb, out);
    k_fin<<<1, KK>>>(ema_cs, ema_dw, counter, out);
}

// round 4
// speedup vs baseline: 1.1419x; 1.0822x over previous
#include <cuda_runtime.h>
#include <math.h>

#define DD 64
#define KK 512
#define NV 65536
#define DECAYF 0.99f
#define EPSF 1e-5f

#define TPB   256
#define ROWT  64
#define XS    68          // x-tile row stride (floats), 16B-aligned (68*4=272)
#define NTILES (NV / ROWT)  // 1024
#define GRID  152

// Output layout (concatenated float32, reference tuple order)
#define OFF_Q      0
#define OFF_LOSS   (NV * DD)
#define OFF_PERP   (OFF_LOSS + 1)
#define OFF_IDX    (OFF_PERP + 1)
#define OFF_NEWEMB (OFF_IDX + NV)
#define OFF_HIDCS  (OFF_NEWEMB + DD*KK)
#define OFF_HIDDW  (OFF_HIDCS + KK)

typedef unsigned long long ull;

// Packed fp32x2 FMA: 2 IEEE fp32 FMAs per instruction, bit-exact vs scalar fmaf.
__device__ __forceinline__ ull ffma2(ull a, ull b, ull c) {
    ull d;
    asm("fma.rn.f32x2 %0, %1, %2, %3;" : "=l"(d) : "l"(a), "l"(b), "l"(c));
    return d;
}
__device__ __forceinline__ ull pack2(float lo, float hi) {
    ull r;
    asm("mov.b64 %0, {%1, %2};" : "=l"(r) : "f"(lo), "f"(hi));
    return r;
}
__device__ __forceinline__ float2 unpack2(ull v) {
    float2 f;
    asm("mov.b64 {%0, %1}, %2;" : "=f"(f.x), "=f"(f.y) : "l"(v));
    return f;
}
// Monotonic float->uint key; idx in low 32 bits => u64-min == (min score, min idx)
__device__ __forceinline__ ull keyf(float s, unsigned idx) {
    unsigned u = __float_as_uint(s);
    u = (u & 0x80000000u) ? ~u : (u | 0x80000000u);
    return ((ull)u << 32) | (ull)idx;
}
__device__ __forceinline__ ull umin64(ull a, ull b) { return a < b ? a : b; }

// Scratch (no allocations allowed -> device globals)
__device__ float g_dw[DD * KK];
__device__ float g_cs[KK];
__device__ float g_loss;

__global__ void k_init() {
    int i = blockIdx.x * blockDim.x + threadIdx.x;   // 8192 threads
    if (i < DD * KK / 4) ((float4*)g_dw)[i] = make_float4(0.f, 0.f, 0.f, 0.f);
    if (i < KK / 4)      ((float4*)g_cs)[i] = make_float4(0.f, 0.f, 0.f, 0.f);
    if (i == 0) g_loss = 0.0f;
}

__global__ void __launch_bounds__(TPB, 1) k_main(
    const float* __restrict__ x, const float* __restrict__ emb,
    float* __restrict__ out)
{
    extern __shared__ float sm[];
    float* es    = sm;                      // [64][512] codebook
    float* esq   = sm + DD * KK;            // [512]
    float* xs    = esq + KK;                // [64][XS] x-tile, transposed
    int*   sbidx = (int*)(xs + DD * XS);    // [64]

    const int t = threadIdx.x;
    const int w = t >> 5;       // warp 0..7 -> rows 8w..8w+7
    const int l = t & 31;       // lane -> code quads 4l, 128+4l (per half)

    // Stage codebook once (persistent blocks)
    {
        const float4* src = (const float4*)emb;
        float4* dst = (float4*)es;
        for (int i = t; i < DD * KK / 4; i += TPB) dst[i] = src[i];
    }
    __syncthreads();
    for (int k = t; k < KK; k += TPB) {
        float s = 0.0f;
        #pragma unroll
        for (int d = 0; d < DD; d++) {
            float v = es[d * KK + k];
            s = fmaf(v, v, s);
        }
        esq[k] = s;
    }
    __syncthreads();

    const ull M2 = pack2(-2.0f, -2.0f);
    float lacc = 0.0f;

    for (int tile = blockIdx.x; tile < NTILES; tile += gridDim.x) {
        // --- load x-tile transposed: xs[d][row] ---
        #pragma unroll
        for (int i = 0; i < 4; i++) {
            int c   = t + TPB * i;          // 0..1023 float4 tasks
            int row = c >> 4;
            int dq  = (c & 15) * 4;
            float4 v = *(const float4*)(x + (size_t)(tile * ROWT + row) * DD + dq);
            xs[(dq + 0) * XS + row] = v.x;
            xs[(dq + 1) * XS + row] = v.y;
            xs[(dq + 2) * XS + row] = v.z;
            xs[(dq + 3) * XS + row] = v.w;
        }
        __syncthreads();

        ull best[8];
        #pragma unroll
        for (int r = 0; r < 8; r++) best[r] = ~0ull;

        #pragma unroll
        for (int h = 0; h < 2; h++) {
            const int cb = 256 * h;
            ull acc[8][4];
            #pragma unroll
            for (int r = 0; r < 8; r++)
                #pragma unroll
                for (int j = 0; j < 4; j++) acc[r][j] = 0ull;

            #pragma unroll 2
            for (int d = 0; d < DD; d++) {
                // broadcast: all lanes read this warp's 8 rows at dim d
                float4 a0 = *(const float4*)(xs + d * XS + 8 * w);
                float4 a1 = *(const float4*)(xs + d * XS + 8 * w + 4);
                // conflict-free: lane l -> code quad 4l (and 128+4l)
                ulonglong2 b0 = *(const ulonglong2*)(es + d * KK + cb + 4 * l);
                ulonglong2 b1 = *(const ulonglong2*)(es + d * KK + cb + 128 + 4 * l);
                ull ax0 = pack2(a0.x, a0.x), ax1 = pack2(a0.y, a0.y);
                ull ax2 = pack2(a0.z, a0.z), ax3 = pack2(a0.w, a0.w);
                ull ax4 = pack2(a1.x, a1.x), ax5 = pack2(a1.y, a1.y);
                ull ax6 = pack2(a1.z, a1.z), ax7 = pack2(a1.w, a1.w);
                ull ax[8] = {ax0, ax1, ax2, ax3, ax4, ax5, ax6, ax7};
                #pragma unroll
                for (int r = 0; r < 8; r++) {
                    acc[r][0] = ffma2(ax[r], b0.x, acc[r][0]);
                    acc[r][1] = ffma2(ax[r], b0.y, acc[r][1]);
                    acc[r][2] = ffma2(ax[r], b1.x, acc[r][2]);
                    acc[r][3] = ffma2(ax[r], b1.y, acc[r][3]);
                }
            }
            // scores: s = ||e||^2 - 2 x.e  (||x||^2 const per row; argmin-safe)
            ulonglong2 eq0 = *(const ulonglong2*)(esq + cb + 4 * l);
            ulonglong2 eq1 = *(const ulonglong2*)(esq + cb + 128 + 4 * l);
            const unsigned c0 = cb + 4 * l, c1 = cb + 128 + 4 * l;
            #pragma unroll
            for (int r = 0; r < 8; r++) {
                float2 s0 = unpack2(ffma2(M2, acc[r][0], eq0.x));
                float2 s1 = unpack2(ffma2(M2, acc[r][1], eq0.y));
                float2 s2 = unpack2(ffma2(M2, acc[r][2], eq1.x));
                float2 s3 = unpack2(ffma2(M2, acc[r][3], eq1.y));
                best[r] = umin64(best[r], keyf(s0.x, c0 + 0));
                best[r] = umin64(best[r], keyf(s0.y, c0 + 1));
                best[r] = umin64(best[r], keyf(s1.x, c0 + 2));
                best[r] = umin64(best[r], keyf(s1.y, c0 + 3));
                best[r] = umin64(best[r], keyf(s2.x, c1 + 0));
                best[r] = umin64(best[r], keyf(s2.y, c1 + 1));
                best[r] = umin64(best[r], keyf(s3.x, c1 + 2));
                best[r] = umin64(best[r], keyf(s3.y, c1 + 3));
            }
        }

        // cross-lane argmin per row (u64 min keeps exact min-idx tie-break)
        #pragma unroll
        for (int r = 0; r < 8; r++) {
            #pragma unroll
            for (int off = 16; off; off >>= 1) {
                ull o = __shfl_xor_sync(0xffffffffu, best[r], off);
                best[r] = umin64(best[r], o);
            }
        }
        if (l == 0) {
            #pragma unroll
            for (int r = 0; r < 8; r++) {
                int bi = (int)(best[r] & 0xffffffffull);
                sbidx[8 * w + r] = bi;
                out[OFF_IDX + tile * ROWT + 8 * w + r] = (float)bi;
                atomicAdd(&g_cs[bi], 1.0f);
            }
        }
        __syncthreads();

        // --- epilogue: quantized gather, loss, dw scatter ---
        #pragma unroll
        for (int i = 0; i < 4; i++) {
            int c   = t + TPB * i;
            int row = c & 63;
            int d4  = (c >> 6) * 4;
            int bi  = sbidx[row];
            float q0 = es[(d4 + 0) * KK + bi];
            float q1 = es[(d4 + 1) * KK + bi];
            float q2 = es[(d4 + 2) * KK + bi];
            float q3 = es[(d4 + 3) * KK + bi];
            float x0 = xs[(d4 + 0) * XS + row];
            float x1 = xs[(d4 + 1) * XS + row];
            float x2 = xs[(d4 + 2) * XS + row];
            float x3 = xs[(d4 + 3) * XS + row];
            float e0 = q0 - x0, e1 = q1 - x1, e2 = q2 - x2, e3 = q3 - x3;
            lacc = fmaf(e0, e0, lacc); lacc = fmaf(e1, e1, lacc);
            lacc = fmaf(e2, e2, lacc); lacc = fmaf(e3, e3, lacc);
            *(float4*)(out + OFF_Q + (size_t)(tile * ROWT + row) * DD + d4)
                = make_float4(q0, q1, q2, q3);
            atomicAdd(&g_dw[(d4 + 0) * KK + bi], x0);
            atomicAdd(&g_dw[(d4 + 1) * KK + bi], x1);
            atomicAdd(&g_dw[(d4 + 2) * KK + bi], x2);
            atomicAdd(&g_dw[(d4 + 3) * KK + bi], x3);
        }
        __syncthreads();
    }

    // loss: warp-reduce then one atomic per warp
    #pragma unroll
    for (int off = 16; off; off >>= 1)
        lacc += __shfl_down_sync(0xffffffffu, lacc, off);
    if (l == 0 && lacc != 0.0f) atomicAdd(&g_loss, lacc);
}

__global__ void k_fin(const float* __restrict__ ema_cs,
                      const float* __restrict__ ema_dw,
                      const int* __restrict__ counter,
                      float* __restrict__ out)
{
    __shared__ float  s_stable[KK];
    __shared__ double s_red[512];
    int t = threadIdx.x;  // exactly KK threads

    double debias = 1.0 - pow(0.99, (double)(counter[0] + 1));

    float cs  = g_cs[t];
    float hid = ema_cs[t] * DECAYF + cs * (1.0f - DECAYF);
    out[OFF_HIDCS + t] = hid;
    float upd = (float)((double)hid / debias);

    s_red[t] = (double)upd;
    __syncthreads();
    for (int s = 256; s > 0; s >>= 1) {
        if (t < s) s_red[t] += s_red[t + s];
        __syncthreads();
    }
    double nsum = s_red[0];
    __syncthreads();

    float stable = (float)(((double)upd + (double)EPSF)
                           / (nsum + (double)KK * (double)EPSF) * nsum);
    s_stable[t] = stable;

    double p = (double)cs / (double)NV;
    s_red[t] = -p * log(p + 1e-10);
    __syncthreads();
    for (int s = 256; s > 0; s >>= 1) {
        if (t < s) s_red[t] += s_red[t + s];
        __syncthreads();
    }
    double ent = s_red[0];

    if (t == 0) {
        out[OFF_PERP] = (float)exp(ent);
        out[OFF_LOSS] = 0.25f * (g_loss / (float)(NV * DD));
    }
    __syncthreads();

    for (int i = t; i < DD * KK; i += blockDim.x) {
        float hdw = ema_dw[i] * DECAYF + g_dw[i] * (1.0f - DECAYF);
        out[OFF_HIDDW + i] = hdw;
        out[OFF_NEWEMB + i] = (float)((double)hdw / debias) / s_stable[i & (KK - 1)];
    }
}

extern "C" void kernel_launch(void* const* d_in, const int* in_sizes, int n_in,
                              void* d_out, int out_size)
{
    const float* x       = (const float*)d_in[0];
    const float* emb     = (const float*)d_in[1];
    const float* ema_cs  = (const float*)d_in[2];
    const float* ema_dw  = (const float*)d_in[3];
    const int*   counter = (const int*)d_in[4];
    float* out = (float*)d_out;

    const int smem = (DD * KK + KK + DD * XS) * (int)sizeof(float)
                   + ROWT * (int)sizeof(int);        // 150,784 B
    cudaFuncSetAttribute(k_main, cudaFuncAttributeMaxDynamicSharedMemorySize, smem);

    k_init<<<16, 512>>>();
    k_main<<<GRID, TPB, smem>>>(x, emb, out);
    k_fin<<<1, KK>>>(ema_cs, ema_dw, counter, out);
}